// round 1
// baseline (speedup 1.0000x reference)
#include <cuda_runtime.h>
#include <cuda_bf16.h>
#include <math.h>

// ---------------------------------------------------------------------------
// Problem constants
// ---------------------------------------------------------------------------
#define B_      2
#define M_      2048
#define DMODEL  1024
#define NH      16
#define DK      64
#define FF      4096
#define ROWS    (B_ * M_)          // 4096
#define MASKF   (-9.765625e11f)    // MASK_VAL / D_MODEL = -1e15/1024
#define INV_D   (1.0f / 1024.0f)
#define LN_EPS  1e-5f

// ---------------------------------------------------------------------------
// Scratch (allocation-free: __device__ globals)
// ---------------------------------------------------------------------------
__device__ float g_Q [ROWS * DMODEL];
__device__ float g_K [ROWS * DMODEL];
__device__ float g_V [ROWS * DMODEL];
__device__ float g_AO[ROWS * DMODEL];
__device__ float g_H1[ROWS * DMODEL];
__device__ float g_F1[ROWS * FF];
__device__ float g_F2[ROWS * DMODEL];
__device__ unsigned char g_mask[ROWS];

// ---------------------------------------------------------------------------
// Mask normalization: handle bool serialized as uint8 OR int32 (OR float32).
// Only reads bytes that are in-bounds under the detected hypothesis.
// ---------------------------------------------------------------------------
__global__ void mask_norm_kernel(const unsigned char* __restrict__ mb, int nelem)
{
    __shared__ int s_gt1, s_off;
    int t = threadIdx.x;
    if (t == 0) { s_gt1 = 0; s_off = 0; }
    __syncthreads();
    int gt1 = 0, off = 0;
    // First nelem bytes are in-bounds under every candidate layout (u8: exactly
    // the buffer; i32/f32: first quarter of the buffer).
    for (int i = t; i < nelem; i += blockDim.x) {
        unsigned char v = mb[i];
        if (v > 1) gt1 = 1;
        if ((i & 3) && v) off = 1;
    }
    if (gt1) atomicOr(&s_gt1, 1);
    if (off) atomicOr(&s_off, 1);
    __syncthreads();
    bool u8 = (!s_gt1) && s_off;   // bytes all in {0,1} AND non-aligned nonzeros
    if (u8) {
        for (int i = t; i < nelem; i += blockDim.x)
            g_mask[i] = mb[i] ? 1 : 0;
    } else {
        const int* mi = (const int*)mb;   // int32 / float32(nonzero-bits) layout
        for (int i = t; i < nelem; i += blockDim.x)
            g_mask[i] = mi[i] ? 1 : 0;
    }
}

// ---------------------------------------------------------------------------
// SGEMM: C[M,N] = A[M,K] @ B[K,N] + bias[N]   (optional ReLU)
// 128x128 tile, BK=8, 256 threads, 8x8 per thread. All dims multiples of 128/8.
// ---------------------------------------------------------------------------
#define BM 128
#define BN 128
#define BK 8

__global__ __launch_bounds__(256, 2)
void sgemm_bias_kernel(const float* __restrict__ A, const float* __restrict__ Bm,
                       const float* __restrict__ bias, float* __restrict__ C,
                       int Mdim, int Ndim, int Kdim, int relu)
{
    __shared__ float As[BK][BM];
    __shared__ float Bs[BK][BN];

    const int t  = threadIdx.x;
    const int bn = blockIdx.x;
    const int bm = blockIdx.y;

    const int arow = t >> 1;            // 0..127
    const int acol = (t & 1) * 4;       // 0 or 4
    const int brow = t >> 5;            // 0..7
    const int bcol = (t & 31) * 4;      // 0..124

    const float* Ag = A  + (size_t)(bm * BM + arow) * Kdim + acol;
    const float* Bg = Bm + (size_t)brow * Ndim + bn * BN + bcol;

    const int tx = t & 15;
    const int ty = t >> 4;

    float acc[8][8];
#pragma unroll
    for (int i = 0; i < 8; i++)
#pragma unroll
        for (int j = 0; j < 8; j++) acc[i][j] = 0.0f;

    for (int kt = 0; kt < Kdim; kt += BK) {
        float4 av = *(const float4*)(Ag + kt);
        float4 bv = *(const float4*)(Bg + (size_t)kt * Ndim);
        As[acol + 0][arow] = av.x;
        As[acol + 1][arow] = av.y;
        As[acol + 2][arow] = av.z;
        As[acol + 3][arow] = av.w;
        *(float4*)&Bs[brow][bcol] = bv;
        __syncthreads();

#pragma unroll
        for (int k = 0; k < BK; k++) {
            float ra[8], rb[8];
            *(float4*)(ra)     = *(const float4*)&As[k][ty * 8];
            *(float4*)(ra + 4) = *(const float4*)&As[k][ty * 8 + 4];
            *(float4*)(rb)     = *(const float4*)&Bs[k][tx * 8];
            *(float4*)(rb + 4) = *(const float4*)&Bs[k][tx * 8 + 4];
#pragma unroll
            for (int i = 0; i < 8; i++)
#pragma unroll
                for (int j = 0; j < 8; j++)
                    acc[i][j] = fmaf(ra[i], rb[j], acc[i][j]);
        }
        __syncthreads();
    }

    float bvals[8];
#pragma unroll
    for (int j = 0; j < 8; j++) bvals[j] = bias[bn * BN + tx * 8 + j];

#pragma unroll
    for (int i = 0; i < 8; i++) {
        int row = bm * BM + ty * 8 + i;
        float* Cr = C + (size_t)row * Ndim + bn * BN + tx * 8;
        float4 o0, o1;
        o0.x = acc[i][0] + bvals[0]; o0.y = acc[i][1] + bvals[1];
        o0.z = acc[i][2] + bvals[2]; o0.w = acc[i][3] + bvals[3];
        o1.x = acc[i][4] + bvals[4]; o1.y = acc[i][5] + bvals[5];
        o1.z = acc[i][6] + bvals[6]; o1.w = acc[i][7] + bvals[7];
        if (relu) {
            o0.x = fmaxf(o0.x, 0.f); o0.y = fmaxf(o0.y, 0.f);
            o0.z = fmaxf(o0.z, 0.f); o0.w = fmaxf(o0.w, 0.f);
            o1.x = fmaxf(o1.x, 0.f); o1.y = fmaxf(o1.y, 0.f);
            o1.z = fmaxf(o1.z, 0.f); o1.w = fmaxf(o1.w, 0.f);
        }
        *(float4*)(Cr)     = o0;
        *(float4*)(Cr + 4) = o1;
    }
}

// ---------------------------------------------------------------------------
// Flash attention (fp32). grid = (B*H, M/64). 256 threads (16x16), each thread
// owns a 4x4 micro-tile. Online softmax; score scale = 1/D_MODEL (reference!).
// Dynamic smem: Qt[64][64] (d-major) | Kt[64][64] (d-major) | Vs[64][64] | Ps[64][68]
// ---------------------------------------------------------------------------
#define ATT_QBLK 64
#define ATT_KBLK 64
#define PS_LD    68
#define ATT_SMEM_FLOATS (4096 * 3 + ATT_KBLK * PS_LD)   // 16640
#define ATT_SMEM_BYTES  (ATT_SMEM_FLOATS * 4)           // 66560

__global__ __launch_bounds__(256, 1)
void attn_kernel()
{
    extern __shared__ float sm[];
    float* Qt = sm;               // [d][q]
    float* Kt = sm + 4096;        // [d][k]
    float* Vs = sm + 8192;        // [k][dv]
    float* Ps = sm + 12288;       // [q][k] with ld=68

    const int t   = threadIdx.x;
    const int tx  = t & 15;
    const int ty  = t >> 4;
    const int bh  = blockIdx.x;          // 0..31
    const int qb  = blockIdx.y;          // 0..31
    const int b   = bh >> 4;             // /NH
    const int h   = bh & 15;

    const int r  = t >> 2;               // 0..63 (tile row handled by this thread)
    const int c0 = (t & 3) * 16;         // base col (of 64) for loads

    // ---- load Q tile (64 q x 64 d), store d-major ----
    {
        const float* Qg = g_Q + ((size_t)(b * M_ + qb * ATT_QBLK + r)) * DMODEL + h * DK + c0;
#pragma unroll
        for (int u = 0; u < 4; u++) {
            float4 v = *(const float4*)(Qg + 4 * u);
            int d = c0 + 4 * u;
            Qt[(d + 0) * 64 + r] = v.x;
            Qt[(d + 1) * 64 + r] = v.y;
            Qt[(d + 2) * 64 + r] = v.z;
            Qt[(d + 3) * 64 + r] = v.w;
        }
    }

    bool mq[4];
#pragma unroll
    for (int i = 0; i < 4; i++)
        mq[i] = g_mask[b * M_ + qb * ATT_QBLK + ty * 4 + i] != 0;

    float O[4][4];
    float mrow[4], lrow[4];
#pragma unroll
    for (int i = 0; i < 4; i++) {
        mrow[i] = -1e30f; lrow[i] = 0.0f;
#pragma unroll
        for (int j = 0; j < 4; j++) O[i][j] = 0.0f;
    }

    const unsigned FULL = 0xffffffffu;

    for (int kb = 0; kb < M_ / ATT_KBLK; kb++) {
        __syncthreads();   // previous PV done before overwriting tiles

        // load K tile (d-major) and V tile (k-major)
        {
            const float* Kg = g_K + ((size_t)(b * M_ + kb * ATT_KBLK + r)) * DMODEL + h * DK + c0;
            const float* Vg = g_V + ((size_t)(b * M_ + kb * ATT_KBLK + r)) * DMODEL + h * DK + c0;
#pragma unroll
            for (int u = 0; u < 4; u++) {
                float4 kv = *(const float4*)(Kg + 4 * u);
                int d = c0 + 4 * u;
                Kt[(d + 0) * 64 + r] = kv.x;
                Kt[(d + 1) * 64 + r] = kv.y;
                Kt[(d + 2) * 64 + r] = kv.z;
                Kt[(d + 3) * 64 + r] = kv.w;
                float4 vv = *(const float4*)(Vg + 4 * u);
                *(float4*)&Vs[r * 64 + d] = vv;
            }
        }
        __syncthreads();

        // ---- S = Q K^T (4x4 per thread) ----
        float s[4][4];
#pragma unroll
        for (int i = 0; i < 4; i++)
#pragma unroll
            for (int j = 0; j < 4; j++) s[i][j] = 0.0f;

#pragma unroll 8
        for (int d = 0; d < 64; d++) {
            float4 qa = *(const float4*)&Qt[d * 64 + ty * 4];
            float4 ka = *(const float4*)&Kt[d * 64 + tx * 4];
            float a[4] = {qa.x, qa.y, qa.z, qa.w};
            float bb[4] = {ka.x, ka.y, ka.z, ka.w};
#pragma unroll
            for (int i = 0; i < 4; i++)
#pragma unroll
                for (int j = 0; j < 4; j++)
                    s[i][j] = fmaf(a[i], bb[j], s[i][j]);
        }

        bool mk[4];
#pragma unroll
        for (int j = 0; j < 4; j++)
            mk[j] = g_mask[b * M_ + kb * ATT_KBLK + tx * 4 + j] != 0;

#pragma unroll
        for (int i = 0; i < 4; i++)
#pragma unroll
            for (int j = 0; j < 4; j++)
                s[i][j] = (mq[i] && mk[j]) ? s[i][j] * INV_D : MASKF;

        // ---- online softmax update (row = 16 consecutive lanes in a warp) ----
#pragma unroll
        for (int i = 0; i < 4; i++) {
            float rmax = fmaxf(fmaxf(s[i][0], s[i][1]), fmaxf(s[i][2], s[i][3]));
#pragma unroll
            for (int o = 1; o < 16; o <<= 1)
                rmax = fmaxf(rmax, __shfl_xor_sync(FULL, rmax, o));
            float mnew = fmaxf(mrow[i], rmax);
            float corr = __expf(mrow[i] - mnew);
            float p[4], psum = 0.0f;
#pragma unroll
            for (int j = 0; j < 4; j++) {
                p[j] = __expf(s[i][j] - mnew);
                psum += p[j];
            }
#pragma unroll
            for (int o = 1; o < 16; o <<= 1)
                psum += __shfl_xor_sync(FULL, psum, o);
            lrow[i] = lrow[i] * corr + psum;
            mrow[i] = mnew;
#pragma unroll
            for (int j = 0; j < 4; j++) O[i][j] *= corr;
            float4 pv = {p[0], p[1], p[2], p[3]};
            *(float4*)&Ps[(ty * 4 + i) * PS_LD + tx * 4] = pv;
        }
        __syncthreads();

        // ---- O += P V ----
#pragma unroll 8
        for (int k = 0; k < 64; k++) {
            float4 vv = *(const float4*)&Vs[k * 64 + tx * 4];
            float vb[4] = {vv.x, vv.y, vv.z, vv.w};
            float pr[4];
#pragma unroll
            for (int i = 0; i < 4; i++) pr[i] = Ps[(ty * 4 + i) * PS_LD + k];
#pragma unroll
            for (int i = 0; i < 4; i++)
#pragma unroll
                for (int j = 0; j < 4; j++)
                    O[i][j] = fmaf(pr[i], vb[j], O[i][j]);
        }
    }

    // ---- finalize ----
#pragma unroll
    for (int i = 0; i < 4; i++) {
        float inv = 1.0f / lrow[i];
        size_t orow = (size_t)(b * M_ + qb * ATT_QBLK + ty * 4 + i);
        float4 ov = {O[i][0] * inv, O[i][1] * inv, O[i][2] * inv, O[i][3] * inv};
        *(float4*)&g_AO[orow * DMODEL + h * DK + tx * 4] = ov;
    }
}

// ---------------------------------------------------------------------------
// out = LayerNorm(a + b) * gamma + beta    (one row of 1024 per block)
// ---------------------------------------------------------------------------
__global__ __launch_bounds__(256)
void add_ln_kernel(const float* __restrict__ A, const float* __restrict__ Bv,
                   const float* __restrict__ gamma, const float* __restrict__ beta,
                   float* __restrict__ Out)
{
    const int row = blockIdx.x;
    const int t   = threadIdx.x;
    const float4* a4 = (const float4*)(A  + (size_t)row * DMODEL);
    const float4* b4 = (const float4*)(Bv + (size_t)row * DMODEL);

    float4 av = a4[t], bv = b4[t];
    float s0 = av.x + bv.x, s1 = av.y + bv.y, s2 = av.z + bv.z, s3 = av.w + bv.w;

    float sum = s0 + s1 + s2 + s3;
    float sq  = s0 * s0 + s1 * s1 + s2 * s2 + s3 * s3;
#pragma unroll
    for (int o = 16; o; o >>= 1) {
        sum += __shfl_xor_sync(0xffffffffu, sum, o);
        sq  += __shfl_xor_sync(0xffffffffu, sq,  o);
    }
    __shared__ float ssum[8], ssq[8];
    __shared__ float smu, srs;
    int wid = t >> 5, lane = t & 31;
    if (lane == 0) { ssum[wid] = sum; ssq[wid] = sq; }
    __syncthreads();
    if (t < 32) {
        float s2_ = (t < 8) ? ssum[t] : 0.0f;
        float q2_ = (t < 8) ? ssq[t]  : 0.0f;
#pragma unroll
        for (int o = 4; o; o >>= 1) {
            s2_ += __shfl_xor_sync(0xffffffffu, s2_, o);
            q2_ += __shfl_xor_sync(0xffffffffu, q2_, o);
        }
        if (t == 0) {
            float mu  = s2_ * (1.0f / DMODEL);
            float var = q2_ * (1.0f / DMODEL) - mu * mu;
            smu = mu;
            srs = rsqrtf(var + LN_EPS);
        }
    }
    __syncthreads();
    float mu = smu, rs = srs;
    float4 g = ((const float4*)gamma)[t];
    float4 be = ((const float4*)beta)[t];
    float4 o;
    o.x = (s0 - mu) * rs * g.x + be.x;
    o.y = (s1 - mu) * rs * g.y + be.y;
    o.z = (s2 - mu) * rs * g.z + be.z;
    o.w = (s3 - mu) * rs * g.w + be.w;
    ((float4*)(Out + (size_t)row * DMODEL))[t] = o;
}

// ---------------------------------------------------------------------------
// Launch
// ---------------------------------------------------------------------------
extern "C" void kernel_launch(void* const* d_in, const int* in_sizes, int n_in,
                              void* d_out, int out_size)
{
    (void)in_sizes; (void)n_in; (void)out_size;
    const float*         x    = (const float*)d_in[0];
    const unsigned char* mb   = (const unsigned char*)d_in[1];
    const float* Wq = (const float*)d_in[2];
    const float* bq = (const float*)d_in[3];
    const float* Wk = (const float*)d_in[4];
    const float* bk = (const float*)d_in[5];
    const float* Wv = (const float*)d_in[6];
    const float* bv = (const float*)d_in[7];
    const float* W1 = (const float*)d_in[8];
    const float* b1 = (const float*)d_in[9];
    const float* W2 = (const float*)d_in[10];
    const float* b2 = (const float*)d_in[11];
    const float* g1 = (const float*)d_in[12];
    const float* be1 = (const float*)d_in[13];
    const float* g2 = (const float*)d_in[14];
    const float* be2 = (const float*)d_in[15];
    float* out = (float*)d_out;

    float *pQ, *pK, *pV, *pAO, *pH1, *pF1, *pF2;
    cudaGetSymbolAddress((void**)&pQ,  g_Q);
    cudaGetSymbolAddress((void**)&pK,  g_K);
    cudaGetSymbolAddress((void**)&pV,  g_V);
    cudaGetSymbolAddress((void**)&pAO, g_AO);
    cudaGetSymbolAddress((void**)&pH1, g_H1);
    cudaGetSymbolAddress((void**)&pF1, g_F1);
    cudaGetSymbolAddress((void**)&pF2, g_F2);

    cudaFuncSetAttribute(attn_kernel,
                         cudaFuncAttributeMaxDynamicSharedMemorySize, ATT_SMEM_BYTES);

    mask_norm_kernel<<<1, 256>>>(mb, ROWS);

    // QKV projections
    dim3 gqkv(DMODEL / BN, ROWS / BM);
    sgemm_bias_kernel<<<gqkv, 256>>>(x, Wq, bq, pQ, ROWS, DMODEL, DMODEL, 0);
    sgemm_bias_kernel<<<gqkv, 256>>>(x, Wk, bk, pK, ROWS, DMODEL, DMODEL, 0);
    sgemm_bias_kernel<<<gqkv, 256>>>(x, Wv, bv, pV, ROWS, DMODEL, DMODEL, 0);

    // attention
    attn_kernel<<<dim3(B_ * NH, M_ / ATT_QBLK), 256, ATT_SMEM_BYTES>>>();

    // h1 = LN(x + attn_out)
    add_ln_kernel<<<ROWS, 256>>>(x, pAO, g1, be1, pH1);

    // FF
    dim3 gff1(FF / BN, ROWS / BM);
    sgemm_bias_kernel<<<gff1, 256>>>(pH1, W1, b1, pF1, ROWS, FF, DMODEL, 1);
    dim3 gff2(DMODEL / BN, ROWS / BM);
    sgemm_bias_kernel<<<gff2, 256>>>(pF1, W2, b2, pF2, ROWS, DMODEL, FF, 0);

    // out = LN(h1 + ff)
    add_ln_kernel<<<ROWS, 256>>>(pH1, pF2, g2, be2, out);
}

// round 5
// speedup vs baseline: 1.5072x; 1.5072x over previous
#include <cuda_runtime.h>
#include <cuda_bf16.h>
#include <math.h>
#include <stdint.h>

// ---------------------------------------------------------------------------
// Problem constants
// ---------------------------------------------------------------------------
#define B_      2
#define M_      2048
#define DMODEL  1024
#define NH      16
#define DK      64
#define FF      4096
#define ROWS    (B_ * M_)          // 4096
#define MASKF   (-9.765625e11f)    // MASK_VAL / D_MODEL
#define INV_D   (1.0f / 1024.0f)
#define LN_EPS  1e-5f

// ---------------------------------------------------------------------------
// Scratch (allocation-free: __device__ globals)
// ---------------------------------------------------------------------------
__device__ float g_Q [ROWS * DMODEL];
__device__ float g_K [ROWS * DMODEL];
__device__ float g_V [ROWS * DMODEL];
__device__ float g_AO[ROWS * DMODEL];
__device__ float g_H1[ROWS * DMODEL];
__device__ float g_F1[ROWS * FF];
__device__ float g_F2[ROWS * DMODEL];
__device__ unsigned char g_mask[ROWS];
__device__ __nv_bfloat16 g_Ah[ROWS * FF];
__device__ __nv_bfloat16 g_Al[ROWS * FF];
__device__ __nv_bfloat16 g_Bh[FF * DMODEL];
__device__ __nv_bfloat16 g_Bl[FF * DMODEL];

// ---------------------------------------------------------------------------
// Helpers
// ---------------------------------------------------------------------------
__device__ __forceinline__ uint32_t smem_u32(const void* p) {
    uint32_t a;
    asm("{ .reg .u64 t; cvta.to.shared.u64 t, %1; cvt.u32.u64 %0, t; }"
        : "=r"(a) : "l"(p));
    return a;
}

__device__ __forceinline__ void cp_async16(uint32_t saddr, const void* g) {
    asm volatile("cp.async.cg.shared.global [%0], [%1], 16;"
                 :: "r"(saddr), "l"(g));
}
#define CP_COMMIT()  asm volatile("cp.async.commit_group;" ::: "memory")
#define CP_WAIT(n)   asm volatile("cp.async.wait_group %0;" :: "n"(n) : "memory")

__device__ __forceinline__ void ldsm_x4(uint32_t* r, uint32_t addr) {
    asm volatile("ldmatrix.sync.aligned.m8n8.x4.shared.b16 {%0,%1,%2,%3}, [%4];"
                 : "=r"(r[0]), "=r"(r[1]), "=r"(r[2]), "=r"(r[3]) : "r"(addr));
}

__device__ __forceinline__ void mma_bf16(float* c, const uint32_t* a, const uint32_t* b) {
    asm volatile(
        "mma.sync.aligned.m16n8k16.row.col.f32.bf16.bf16.f32 "
        "{%0,%1,%2,%3}, {%4,%5,%6,%7}, {%8,%9}, {%0,%1,%2,%3};"
        : "+f"(c[0]), "+f"(c[1]), "+f"(c[2]), "+f"(c[3])
        : "r"(a[0]), "r"(a[1]), "r"(a[2]), "r"(a[3]), "r"(b[0]), "r"(b[1]));
}

// ---------------------------------------------------------------------------
// Mask normalization (unchanged, known-correct)
// ---------------------------------------------------------------------------
__global__ void mask_norm_kernel(const unsigned char* __restrict__ mb, int nelem)
{
    __shared__ int s_gt1, s_off;
    int t = threadIdx.x;
    if (t == 0) { s_gt1 = 0; s_off = 0; }
    __syncthreads();
    int gt1 = 0, off = 0;
    for (int i = t; i < nelem; i += blockDim.x) {
        unsigned char v = mb[i];
        if (v > 1) gt1 = 1;
        if ((i & 3) && v) off = 1;
    }
    if (gt1) atomicOr(&s_gt1, 1);
    if (off) atomicOr(&s_off, 1);
    __syncthreads();
    bool u8 = (!s_gt1) && s_off;
    if (u8) {
        for (int i = t; i < nelem; i += blockDim.x)
            g_mask[i] = mb[i] ? 1 : 0;
    } else {
        const int* mi = (const int*)mb;
        for (int i = t; i < nelem; i += blockDim.x)
            g_mask[i] = mi[i] ? 1 : 0;
    }
}

// ---------------------------------------------------------------------------
// fp32 -> bf16 hi/lo split (A operands)
// ---------------------------------------------------------------------------
__global__ __launch_bounds__(256)
void conv_split_kernel(const float* __restrict__ src,
                       __nv_bfloat16* __restrict__ hi, __nv_bfloat16* __restrict__ lo,
                       int n4)
{
    int i = blockIdx.x * 256 + threadIdx.x;
    if (i >= n4) return;
    float4 v = ((const float4*)src)[i];
    __nv_bfloat16 h0 = __float2bfloat16(v.x);
    __nv_bfloat16 h1 = __float2bfloat16(v.y);
    __nv_bfloat16 h2 = __float2bfloat16(v.z);
    __nv_bfloat16 h3 = __float2bfloat16(v.w);
    __nv_bfloat16 l0 = __float2bfloat16(v.x - __bfloat162float(h0));
    __nv_bfloat16 l1 = __float2bfloat16(v.y - __bfloat162float(h1));
    __nv_bfloat16 l2 = __float2bfloat16(v.z - __bfloat162float(h2));
    __nv_bfloat16 l3 = __float2bfloat16(v.w - __bfloat162float(h3));
    __nv_bfloat162* H = (__nv_bfloat162*)hi;
    __nv_bfloat162* L = (__nv_bfloat162*)lo;
    H[2 * i]     = __nv_bfloat162(h0, h1);
    H[2 * i + 1] = __nv_bfloat162(h2, h3);
    L[2 * i]     = __nv_bfloat162(l0, l1);
    L[2 * i + 1] = __nv_bfloat162(l2, l3);
}

// ---------------------------------------------------------------------------
// Weight transpose + split: src[K,N] fp32 -> hi/lo [N,K] bf16
// ---------------------------------------------------------------------------
__global__ __launch_bounds__(256)
void convT_split_kernel(const float* __restrict__ src,
                        __nv_bfloat16* __restrict__ hi, __nv_bfloat16* __restrict__ lo,
                        int Kdim, int Ndim)
{
    __shared__ float tile[32][33];
    int n0 = blockIdx.x * 32, k0 = blockIdx.y * 32;
    int x = threadIdx.x, y = threadIdx.y;   // 32 x 8
#pragma unroll
    for (int j = 0; j < 32; j += 8)
        tile[y + j][x] = src[(size_t)(k0 + y + j) * Ndim + n0 + x];
    __syncthreads();
#pragma unroll
    for (int j = 0; j < 32; j += 8) {
        float v = tile[x][y + j];
        __nv_bfloat16 h = __float2bfloat16(v);
        __nv_bfloat16 l = __float2bfloat16(v - __bfloat162float(h));
        size_t o = (size_t)(n0 + y + j) * Kdim + k0 + x;
        hi[o] = h; lo[o] = l;
    }
}

// ---------------------------------------------------------------------------
// HMMA GEMM: C[M,N] = A[M,K] @ Bt[N,K]^T + bias (opt ReLU), bf16x3 split.
// 128x128x32 tile, 8 warps (4x2), warp tile 32x64. cp.async double-buffered.
// K loop runs 3x over splits: (Ah,Bh), (Al,Bh), (Ah,Bl).
// ---------------------------------------------------------------------------
#define HLD 40   // padded row stride in bf16 elements

__global__ __launch_bounds__(256, 2)
void hgemm_bf16x3_kernel(const __nv_bfloat16* __restrict__ Ahm,
                         const __nv_bfloat16* __restrict__ Alm,
                         const __nv_bfloat16* __restrict__ Bhm,
                         const __nv_bfloat16* __restrict__ Blm,
                         const float* __restrict__ bias, float* __restrict__ C,
                         int Ndim, int Kdim, int relu)
{
    __shared__ __nv_bfloat16 sA[2][128][HLD];
    __shared__ __nv_bfloat16 sB[2][128][HLD];

    const int tid  = threadIdx.x;
    const int lane = tid & 31;
    const int wid  = tid >> 5;
    const int bm = blockIdx.y, bn = blockIdx.x;
    const int wm = (wid >> 1) * 32;     // warp M offset (0,32,64,96)
    const int wn = (wid & 1) * 64;      // warp N offset (0,64)

    const int nk = Kdim >> 5;
    const int nIter = 3 * nk;

    const int lrow = tid >> 2;          // 0..63 (with u offset -> 0..127)
    const int lch  = tid & 3;

    float acc[2][8][4];
#pragma unroll
    for (int mi = 0; mi < 2; mi++)
#pragma unroll
        for (int nj = 0; nj < 8; nj++)
#pragma unroll
            for (int q = 0; q < 4; q++) acc[mi][nj][q] = 0.0f;

    // stage loader
    auto load_stage = [&](int i, int buf) {
        int s  = i / nk;
        int kt = i - s * nk;
        const __nv_bfloat16* pa = (s == 1 ? Alm : Ahm) + (size_t)(bm * 128) * Kdim + kt * 32;
        const __nv_bfloat16* pb = (s == 2 ? Blm : Bhm) + (size_t)(bn * 128) * Kdim + kt * 32;
#pragma unroll
        for (int u = 0; u < 2; u++) {
            int row = lrow + 64 * u;
            cp_async16(smem_u32(&sA[buf][row][lch * 8]), pa + (size_t)row * Kdim + lch * 8);
            cp_async16(smem_u32(&sB[buf][row][lch * 8]), pb + (size_t)row * Kdim + lch * 8);
        }
    };

    load_stage(0, 0);
    CP_COMMIT();

    for (int i = 0; i < nIter; i++) {
        const int buf = i & 1;
        if (i + 1 < nIter) {
            load_stage(i + 1, buf ^ 1);
            CP_COMMIT();
            CP_WAIT(1);
        } else {
            CP_WAIT(0);
        }
        __syncthreads();

#pragma unroll
        for (int k = 0; k < 32; k += 16) {
            uint32_t afr[2][4];
#pragma unroll
            for (int mi = 0; mi < 2; mi++) {
                uint32_t addr = smem_u32(
                    &sA[buf][wm + mi * 16 + (lane & 15)][k + (lane >> 4) * 8]);
                ldsm_x4(afr[mi], addr);
            }
            uint32_t bfr[8][2];
#pragma unroll
            for (int ni = 0; ni < 4; ni++) {
                uint32_t r[4];
                uint32_t addr = smem_u32(
                    &sB[buf][wn + ni * 16 + (lane & 7) + ((lane >> 4) & 1) * 8]
                       [k + ((lane >> 3) & 1) * 8]);
                ldsm_x4(r, addr);
                bfr[2 * ni][0]     = r[0];
                bfr[2 * ni][1]     = r[1];
                bfr[2 * ni + 1][0] = r[2];
                bfr[2 * ni + 1][1] = r[3];
            }
#pragma unroll
            for (int mi = 0; mi < 2; mi++)
#pragma unroll
                for (int nj = 0; nj < 8; nj++)
                    mma_bf16(acc[mi][nj], afr[mi], bfr[nj]);
        }
        __syncthreads();
    }

    // epilogue: bias + optional relu, write fp32
#pragma unroll
    for (int mi = 0; mi < 2; mi++) {
#pragma unroll
        for (int nj = 0; nj < 8; nj++) {
            int row0 = bm * 128 + wm + mi * 16 + (lane >> 2);
            int col  = bn * 128 + wn + nj * 8 + 2 * (lane & 3);
            float b0 = bias[col], b1 = bias[col + 1];
            float2 v0 = {acc[mi][nj][0] + b0, acc[mi][nj][1] + b1};
            float2 v1 = {acc[mi][nj][2] + b0, acc[mi][nj][3] + b1};
            if (relu) {
                v0.x = fmaxf(v0.x, 0.f); v0.y = fmaxf(v0.y, 0.f);
                v1.x = fmaxf(v1.x, 0.f); v1.y = fmaxf(v1.y, 0.f);
            }
            *(float2*)&C[(size_t)row0 * Ndim + col]       = v0;
            *(float2*)&C[(size_t)(row0 + 8) * Ndim + col] = v1;
        }
    }
}

// ---------------------------------------------------------------------------
// Flash attention (fp32) — unchanged from R1 (known-correct)
// ---------------------------------------------------------------------------
#define ATT_QBLK 64
#define ATT_KBLK 64
#define PS_LD    68
#define ATT_SMEM_FLOATS (4096 * 3 + ATT_KBLK * PS_LD)
#define ATT_SMEM_BYTES  (ATT_SMEM_FLOATS * 4)

__global__ __launch_bounds__(256, 1)
void attn_kernel()
{
    extern __shared__ float sm[];
    float* Qt = sm;
    float* Kt = sm + 4096;
    float* Vs = sm + 8192;
    float* Ps = sm + 12288;

    const int t   = threadIdx.x;
    const int tx  = t & 15;
    const int ty  = t >> 4;
    const int bh  = blockIdx.x;
    const int qb  = blockIdx.y;
    const int b   = bh >> 4;
    const int h   = bh & 15;

    const int r  = t >> 2;
    const int c0 = (t & 3) * 16;

    {
        const float* Qg = g_Q + ((size_t)(b * M_ + qb * ATT_QBLK + r)) * DMODEL + h * DK + c0;
#pragma unroll
        for (int u = 0; u < 4; u++) {
            float4 v = *(const float4*)(Qg + 4 * u);
            int d = c0 + 4 * u;
            Qt[(d + 0) * 64 + r] = v.x;
            Qt[(d + 1) * 64 + r] = v.y;
            Qt[(d + 2) * 64 + r] = v.z;
            Qt[(d + 3) * 64 + r] = v.w;
        }
    }

    bool mq[4];
#pragma unroll
    for (int i = 0; i < 4; i++)
        mq[i] = g_mask[b * M_ + qb * ATT_QBLK + ty * 4 + i] != 0;

    float O[4][4];
    float mrow[4], lrow[4];
#pragma unroll
    for (int i = 0; i < 4; i++) {
        mrow[i] = -1e30f; lrow[i] = 0.0f;
#pragma unroll
        for (int j = 0; j < 4; j++) O[i][j] = 0.0f;
    }

    const unsigned FULL = 0xffffffffu;

    for (int kb = 0; kb < M_ / ATT_KBLK; kb++) {
        __syncthreads();

        {
            const float* Kg = g_K + ((size_t)(b * M_ + kb * ATT_KBLK + r)) * DMODEL + h * DK + c0;
            const float* Vg = g_V + ((size_t)(b * M_ + kb * ATT_KBLK + r)) * DMODEL + h * DK + c0;
#pragma unroll
            for (int u = 0; u < 4; u++) {
                float4 kv = *(const float4*)(Kg + 4 * u);
                int d = c0 + 4 * u;
                Kt[(d + 0) * 64 + r] = kv.x;
                Kt[(d + 1) * 64 + r] = kv.y;
                Kt[(d + 2) * 64 + r] = kv.z;
                Kt[(d + 3) * 64 + r] = kv.w;
                float4 vv = *(const float4*)(Vg + 4 * u);
                *(float4*)&Vs[r * 64 + d] = vv;
            }
        }
        __syncthreads();

        float s[4][4];
#pragma unroll
        for (int i = 0; i < 4; i++)
#pragma unroll
            for (int j = 0; j < 4; j++) s[i][j] = 0.0f;

#pragma unroll 8
        for (int d = 0; d < 64; d++) {
            float4 qa = *(const float4*)&Qt[d * 64 + ty * 4];
            float4 ka = *(const float4*)&Kt[d * 64 + tx * 4];
            float a[4] = {qa.x, qa.y, qa.z, qa.w};
            float bb[4] = {ka.x, ka.y, ka.z, ka.w};
#pragma unroll
            for (int i = 0; i < 4; i++)
#pragma unroll
                for (int j = 0; j < 4; j++)
                    s[i][j] = fmaf(a[i], bb[j], s[i][j]);
        }

        bool mk[4];
#pragma unroll
        for (int j = 0; j < 4; j++)
            mk[j] = g_mask[b * M_ + kb * ATT_KBLK + tx * 4 + j] != 0;

#pragma unroll
        for (int i = 0; i < 4; i++)
#pragma unroll
            for (int j = 0; j < 4; j++)
                s[i][j] = (mq[i] && mk[j]) ? s[i][j] * INV_D : MASKF;

#pragma unroll
        for (int i = 0; i < 4; i++) {
            float rmax = fmaxf(fmaxf(s[i][0], s[i][1]), fmaxf(s[i][2], s[i][3]));
#pragma unroll
            for (int o = 1; o < 16; o <<= 1)
                rmax = fmaxf(rmax, __shfl_xor_sync(FULL, rmax, o));
            float mnew = fmaxf(mrow[i], rmax);
            float corr = __expf(mrow[i] - mnew);
            float p[4], psum = 0.0f;
#pragma unroll
            for (int j = 0; j < 4; j++) {
                p[j] = __expf(s[i][j] - mnew);
                psum += p[j];
            }
#pragma unroll
            for (int o = 1; o < 16; o <<= 1)
                psum += __shfl_xor_sync(FULL, psum, o);
            lrow[i] = lrow[i] * corr + psum;
            mrow[i] = mnew;
#pragma unroll
            for (int j = 0; j < 4; j++) O[i][j] *= corr;
            float4 pv = {p[0], p[1], p[2], p[3]};
            *(float4*)&Ps[(ty * 4 + i) * PS_LD + tx * 4] = pv;
        }
        __syncthreads();

#pragma unroll 8
        for (int k = 0; k < 64; k++) {
            float4 vv = *(const float4*)&Vs[k * 64 + tx * 4];
            float vb[4] = {vv.x, vv.y, vv.z, vv.w};
            float pr[4];
#pragma unroll
            for (int i = 0; i < 4; i++) pr[i] = Ps[(ty * 4 + i) * PS_LD + k];
#pragma unroll
            for (int i = 0; i < 4; i++)
#pragma unroll
                for (int j = 0; j < 4; j++)
                    O[i][j] = fmaf(pr[i], vb[j], O[i][j]);
        }
    }

#pragma unroll
    for (int i = 0; i < 4; i++) {
        float inv = 1.0f / lrow[i];
        size_t orow = (size_t)(b * M_ + qb * ATT_QBLK + ty * 4 + i);
        float4 ov = {O[i][0] * inv, O[i][1] * inv, O[i][2] * inv, O[i][3] * inv};
        *(float4*)&g_AO[orow * DMODEL + h * DK + tx * 4] = ov;
    }
}

// ---------------------------------------------------------------------------
// out = LayerNorm(a + b) * gamma + beta (unchanged)
// ---------------------------------------------------------------------------
__global__ __launch_bounds__(256)
void add_ln_kernel(const float* __restrict__ A, const float* __restrict__ Bv,
                   const float* __restrict__ gamma, const float* __restrict__ beta,
                   float* __restrict__ Out)
{
    const int row = blockIdx.x;
    const int t   = threadIdx.x;
    const float4* a4 = (const float4*)(A  + (size_t)row * DMODEL);
    const float4* b4 = (const float4*)(Bv + (size_t)row * DMODEL);

    float4 av = a4[t], bv = b4[t];
    float s0 = av.x + bv.x, s1 = av.y + bv.y, s2 = av.z + bv.z, s3 = av.w + bv.w;

    float sum = s0 + s1 + s2 + s3;
    float sq  = s0 * s0 + s1 * s1 + s2 * s2 + s3 * s3;
#pragma unroll
    for (int o = 16; o; o >>= 1) {
        sum += __shfl_xor_sync(0xffffffffu, sum, o);
        sq  += __shfl_xor_sync(0xffffffffu, sq,  o);
    }
    __shared__ float ssum[8], ssq[8];
    __shared__ float smu, srs;
    int wid = t >> 5, lane = t & 31;
    if (lane == 0) { ssum[wid] = sum; ssq[wid] = sq; }
    __syncthreads();
    if (t < 32) {
        float s2_ = (t < 8) ? ssum[t] : 0.0f;
        float q2_ = (t < 8) ? ssq[t]  : 0.0f;
#pragma unroll
        for (int o = 4; o; o >>= 1) {
            s2_ += __shfl_xor_sync(0xffffffffu, s2_, o);
            q2_ += __shfl_xor_sync(0xffffffffu, q2_, o);
        }
        if (t == 0) {
            float mu  = s2_ * (1.0f / DMODEL);
            float var = q2_ * (1.0f / DMODEL) - mu * mu;
            smu = mu;
            srs = rsqrtf(var + LN_EPS);
        }
    }
    __syncthreads();
    float mu = smu, rs = srs;
    float4 g = ((const float4*)gamma)[t];
    float4 be = ((const float4*)beta)[t];
    float4 o;
    o.x = (s0 - mu) * rs * g.x + be.x;
    o.y = (s1 - mu) * rs * g.y + be.y;
    o.z = (s2 - mu) * rs * g.z + be.z;
    o.w = (s3 - mu) * rs * g.w + be.w;
    ((float4*)(Out + (size_t)row * DMODEL))[t] = o;
}

// ---------------------------------------------------------------------------
// Launch
// ---------------------------------------------------------------------------
extern "C" void kernel_launch(void* const* d_in, const int* in_sizes, int n_in,
                              void* d_out, int out_size)
{
    (void)in_sizes; (void)n_in; (void)out_size;
    const float*         x    = (const float*)d_in[0];
    const unsigned char* mb   = (const unsigned char*)d_in[1];
    const float* Wq = (const float*)d_in[2];
    const float* bq = (const float*)d_in[3];
    const float* Wk = (const float*)d_in[4];
    const float* bk = (const float*)d_in[5];
    const float* Wv = (const float*)d_in[6];
    const float* bv = (const float*)d_in[7];
    const float* W1 = (const float*)d_in[8];
    const float* b1 = (const float*)d_in[9];
    const float* W2 = (const float*)d_in[10];
    const float* b2 = (const float*)d_in[11];
    const float* g1 = (const float*)d_in[12];
    const float* be1 = (const float*)d_in[13];
    const float* g2 = (const float*)d_in[14];
    const float* be2 = (const float*)d_in[15];
    float* out = (float*)d_out;

    float *pQ, *pK, *pV, *pAO, *pH1, *pF1, *pF2;
    __nv_bfloat16 *pAh, *pAl, *pBh, *pBl;
    cudaGetSymbolAddress((void**)&pQ,  g_Q);
    cudaGetSymbolAddress((void**)&pK,  g_K);
    cudaGetSymbolAddress((void**)&pV,  g_V);
    cudaGetSymbolAddress((void**)&pAO, g_AO);
    cudaGetSymbolAddress((void**)&pH1, g_H1);
    cudaGetSymbolAddress((void**)&pF1, g_F1);
    cudaGetSymbolAddress((void**)&pF2, g_F2);
    cudaGetSymbolAddress((void**)&pAh, g_Ah);
    cudaGetSymbolAddress((void**)&pAl, g_Al);
    cudaGetSymbolAddress((void**)&pBh, g_Bh);
    cudaGetSymbolAddress((void**)&pBl, g_Bl);

    cudaFuncSetAttribute(attn_kernel,
                         cudaFuncAttributeMaxDynamicSharedMemorySize, ATT_SMEM_BYTES);

    mask_norm_kernel<<<1, 256>>>(mb, ROWS);

    // ---- split x (A operand for QKV) ----
    conv_split_kernel<<<(ROWS * DMODEL / 4 + 255) / 256, 256>>>(x, pAh, pAl, ROWS * DMODEL / 4);

    dim3 tg32(DMODEL / 32, DMODEL / 32);
    dim3 tb(32, 8);
    dim3 gqkv(DMODEL / 128, ROWS / 128);

    convT_split_kernel<<<tg32, tb>>>(Wq, pBh, pBl, DMODEL, DMODEL);
    hgemm_bf16x3_kernel<<<gqkv, 256>>>(pAh, pAl, pBh, pBl, bq, pQ, DMODEL, DMODEL, 0);
    convT_split_kernel<<<tg32, tb>>>(Wk, pBh, pBl, DMODEL, DMODEL);
    hgemm_bf16x3_kernel<<<gqkv, 256>>>(pAh, pAl, pBh, pBl, bk, pK, DMODEL, DMODEL, 0);
    convT_split_kernel<<<tg32, tb>>>(Wv, pBh, pBl, DMODEL, DMODEL);
    hgemm_bf16x3_kernel<<<gqkv, 256>>>(pAh, pAl, pBh, pBl, bv, pV, DMODEL, DMODEL, 0);

    // ---- attention (fp32) ----
    attn_kernel<<<dim3(B_ * NH, M_ / ATT_QBLK), 256, ATT_SMEM_BYTES>>>();

    // ---- h1 = LN(x + attn_out) ----
    add_ln_kernel<<<ROWS, 256>>>(x, pAO, g1, be1, pH1);

    // ---- FF1: relu(h1 @ W1 + b1) ----
    conv_split_kernel<<<(ROWS * DMODEL / 4 + 255) / 256, 256>>>(pH1, pAh, pAl, ROWS * DMODEL / 4);
    convT_split_kernel<<<dim3(FF / 32, DMODEL / 32), tb>>>(W1, pBh, pBl, DMODEL, FF);
    hgemm_bf16x3_kernel<<<dim3(FF / 128, ROWS / 128), 256>>>(
        pAh, pAl, pBh, pBl, b1, pF1, FF, DMODEL, 1);

    // ---- FF2: f1 @ W2 + b2 ----
    conv_split_kernel<<<(ROWS * FF / 4 + 255) / 256, 256>>>(pF1, pAh, pAl, ROWS * FF / 4);
    convT_split_kernel<<<dim3(DMODEL / 32, FF / 32), tb>>>(W2, pBh, pBl, FF, DMODEL);
    hgemm_bf16x3_kernel<<<dim3(DMODEL / 128, ROWS / 128), 256>>>(
        pAh, pAl, pBh, pBl, b2, pF2, DMODEL, FF, 0);

    // ---- out = LN(h1 + ff) ----
    add_ln_kernel<<<ROWS, 256>>>(pH1, pF2, g2, be2, out);
}

// round 8
// speedup vs baseline: 2.4450x; 1.6222x over previous
#include <cuda_runtime.h>
#include <cuda_bf16.h>
#include <math.h>
#include <stdint.h>

// ---------------------------------------------------------------------------
// Problem constants
// ---------------------------------------------------------------------------
#define B_      2
#define M_      2048
#define DMODEL  1024
#define NH      16
#define DK      64
#define FF      4096
#define ROWS    (B_ * M_)          // 4096
#define MASKF   (-9.765625e11f)    // MASK_VAL / D_MODEL
#define INV_D   (1.0f / 1024.0f)
#define LN_EPS  1e-5f

// ---------------------------------------------------------------------------
// Scratch (allocation-free: __device__ globals)
// ---------------------------------------------------------------------------
__device__ float g_Q [ROWS * DMODEL];
__device__ float g_K [ROWS * DMODEL];
__device__ float g_V [ROWS * DMODEL];
__device__ float g_AO[ROWS * DMODEL];
__device__ float g_H1[ROWS * DMODEL];
__device__ float g_F1[ROWS * FF];
__device__ float g_F2[ROWS * DMODEL];
__device__ unsigned char g_mask[ROWS];
__device__ __nv_bfloat16 g_Ah[ROWS * FF];
__device__ __nv_bfloat16 g_Al[ROWS * FF];
__device__ __nv_bfloat16 g_Bh[FF * DMODEL];
__device__ __nv_bfloat16 g_Bl[FF * DMODEL];

// ---------------------------------------------------------------------------
// Helpers
// ---------------------------------------------------------------------------
__device__ __forceinline__ uint32_t smem_u32(const void* p) {
    uint32_t a;
    asm("{ .reg .u64 t; cvta.to.shared.u64 t, %1; cvt.u32.u64 %0, t; }"
        : "=r"(a) : "l"(p));
    return a;
}

__device__ __forceinline__ void cp_async16(uint32_t saddr, const void* g) {
    asm volatile("cp.async.cg.shared.global [%0], [%1], 16;"
                 :: "r"(saddr), "l"(g));
}
#define CP_COMMIT()  asm volatile("cp.async.commit_group;" ::: "memory")
#define CP_WAIT(n)   asm volatile("cp.async.wait_group %0;" :: "n"(n) : "memory")

__device__ __forceinline__ void ldsm_x4(uint32_t* r, uint32_t addr) {
    asm volatile("ldmatrix.sync.aligned.m8n8.x4.shared.b16 {%0,%1,%2,%3}, [%4];"
                 : "=r"(r[0]), "=r"(r[1]), "=r"(r[2]), "=r"(r[3]) : "r"(addr));
}

__device__ __forceinline__ void ldsm_x4_t(uint32_t* r, uint32_t addr) {
    asm volatile("ldmatrix.sync.aligned.m8n8.x4.trans.shared.b16 {%0,%1,%2,%3}, [%4];"
                 : "=r"(r[0]), "=r"(r[1]), "=r"(r[2]), "=r"(r[3]) : "r"(addr));
}

__device__ __forceinline__ void mma_bf16(float* c, const uint32_t* a, const uint32_t* b) {
    asm volatile(
        "mma.sync.aligned.m16n8k16.row.col.f32.bf16.bf16.f32 "
        "{%0,%1,%2,%3}, {%4,%5,%6,%7}, {%8,%9}, {%0,%1,%2,%3};"
        : "+f"(c[0]), "+f"(c[1]), "+f"(c[2]), "+f"(c[3])
        : "r"(a[0]), "r"(a[1]), "r"(a[2]), "r"(a[3]), "r"(b[0]), "r"(b[1]));
}

// pack two fp32 -> bf16x2 (lo in low half)
__device__ __forceinline__ uint32_t cvt_bf2(float lo, float hi) {
    uint32_t r;
    asm("cvt.rn.bf16x2.f32 %0, %1, %2;" : "=r"(r) : "f"(hi), "f"(lo));
    return r;
}

// ---------------------------------------------------------------------------
// Mask normalization (unchanged, known-correct)
// ---------------------------------------------------------------------------
__global__ void mask_norm_kernel(const unsigned char* __restrict__ mb, int nelem)
{
    __shared__ int s_gt1, s_off;
    int t = threadIdx.x;
    if (t == 0) { s_gt1 = 0; s_off = 0; }
    __syncthreads();
    int gt1 = 0, off = 0;
    for (int i = t; i < nelem; i += blockDim.x) {
        unsigned char v = mb[i];
        if (v > 1) gt1 = 1;
        if ((i & 3) && v) off = 1;
    }
    if (gt1) atomicOr(&s_gt1, 1);
    if (off) atomicOr(&s_off, 1);
    __syncthreads();
    bool u8 = (!s_gt1) && s_off;
    if (u8) {
        for (int i = t; i < nelem; i += blockDim.x)
            g_mask[i] = mb[i] ? 1 : 0;
    } else {
        const int* mi = (const int*)mb;
        for (int i = t; i < nelem; i += blockDim.x)
            g_mask[i] = mi[i] ? 1 : 0;
    }
}

// ---------------------------------------------------------------------------
// fp32 -> bf16 hi/lo split (A operands)
// ---------------------------------------------------------------------------
__global__ __launch_bounds__(256)
void conv_split_kernel(const float* __restrict__ src,
                       __nv_bfloat16* __restrict__ hi, __nv_bfloat16* __restrict__ lo,
                       int n4)
{
    int i = blockIdx.x * 256 + threadIdx.x;
    if (i >= n4) return;
    float4 v = ((const float4*)src)[i];
    __nv_bfloat16 h0 = __float2bfloat16(v.x);
    __nv_bfloat16 h1 = __float2bfloat16(v.y);
    __nv_bfloat16 h2 = __float2bfloat16(v.z);
    __nv_bfloat16 h3 = __float2bfloat16(v.w);
    __nv_bfloat16 l0 = __float2bfloat16(v.x - __bfloat162float(h0));
    __nv_bfloat16 l1 = __float2bfloat16(v.y - __bfloat162float(h1));
    __nv_bfloat16 l2 = __float2bfloat16(v.z - __bfloat162float(h2));
    __nv_bfloat16 l3 = __float2bfloat16(v.w - __bfloat162float(h3));
    __nv_bfloat162* H = (__nv_bfloat162*)hi;
    __nv_bfloat162* L = (__nv_bfloat162*)lo;
    H[2 * i]     = __nv_bfloat162(h0, h1);
    H[2 * i + 1] = __nv_bfloat162(h2, h3);
    L[2 * i]     = __nv_bfloat162(l0, l1);
    L[2 * i + 1] = __nv_bfloat162(l2, l3);
}

// ---------------------------------------------------------------------------
// Weight transpose + split: src[K,N] fp32 -> hi/lo [N,K] bf16
// ---------------------------------------------------------------------------
__global__ __launch_bounds__(256)
void convT_split_kernel(const float* __restrict__ src,
                        __nv_bfloat16* __restrict__ hi, __nv_bfloat16* __restrict__ lo,
                        int Kdim, int Ndim)
{
    __shared__ float tile[32][33];
    int n0 = blockIdx.x * 32, k0 = blockIdx.y * 32;
    int x = threadIdx.x, y = threadIdx.y;   // 32 x 8
#pragma unroll
    for (int j = 0; j < 32; j += 8)
        tile[y + j][x] = src[(size_t)(k0 + y + j) * Ndim + n0 + x];
    __syncthreads();
#pragma unroll
    for (int j = 0; j < 32; j += 8) {
        float v = tile[x][y + j];
        __nv_bfloat16 h = __float2bfloat16(v);
        __nv_bfloat16 l = __float2bfloat16(v - __bfloat162float(h));
        size_t o = (size_t)(n0 + y + j) * Kdim + k0 + x;
        hi[o] = h; lo[o] = l;
    }
}

// ---------------------------------------------------------------------------
// HMMA GEMM (unchanged from R5, known-correct)
// ---------------------------------------------------------------------------
#define HLD 40

__global__ __launch_bounds__(256, 2)
void hgemm_bf16x3_kernel(const __nv_bfloat16* __restrict__ Ahm,
                         const __nv_bfloat16* __restrict__ Alm,
                         const __nv_bfloat16* __restrict__ Bhm,
                         const __nv_bfloat16* __restrict__ Blm,
                         const float* __restrict__ bias, float* __restrict__ C,
                         int Ndim, int Kdim, int relu)
{
    __shared__ __nv_bfloat16 sA[2][128][HLD];
    __shared__ __nv_bfloat16 sB[2][128][HLD];

    const int tid  = threadIdx.x;
    const int lane = tid & 31;
    const int wid  = tid >> 5;
    const int bm = blockIdx.y, bn = blockIdx.x;
    const int wm = (wid >> 1) * 32;
    const int wn = (wid & 1) * 64;

    const int nk = Kdim >> 5;
    const int nIter = 3 * nk;

    const int lrow = tid >> 2;
    const int lch  = tid & 3;

    float acc[2][8][4];
#pragma unroll
    for (int mi = 0; mi < 2; mi++)
#pragma unroll
        for (int nj = 0; nj < 8; nj++)
#pragma unroll
            for (int q = 0; q < 4; q++) acc[mi][nj][q] = 0.0f;

    auto load_stage = [&](int i, int buf) {
        int s  = i / nk;
        int kt = i - s * nk;
        const __nv_bfloat16* pa = (s == 1 ? Alm : Ahm) + (size_t)(bm * 128) * Kdim + kt * 32;
        const __nv_bfloat16* pb = (s == 2 ? Blm : Bhm) + (size_t)(bn * 128) * Kdim + kt * 32;
#pragma unroll
        for (int u = 0; u < 2; u++) {
            int row = lrow + 64 * u;
            cp_async16(smem_u32(&sA[buf][row][lch * 8]), pa + (size_t)row * Kdim + lch * 8);
            cp_async16(smem_u32(&sB[buf][row][lch * 8]), pb + (size_t)row * Kdim + lch * 8);
        }
    };

    load_stage(0, 0);
    CP_COMMIT();

    for (int i = 0; i < nIter; i++) {
        const int buf = i & 1;
        if (i + 1 < nIter) {
            load_stage(i + 1, buf ^ 1);
            CP_COMMIT();
            CP_WAIT(1);
        } else {
            CP_WAIT(0);
        }
        __syncthreads();

#pragma unroll
        for (int k = 0; k < 32; k += 16) {
            uint32_t afr[2][4];
#pragma unroll
            for (int mi = 0; mi < 2; mi++) {
                uint32_t addr = smem_u32(
                    &sA[buf][wm + mi * 16 + (lane & 15)][k + (lane >> 4) * 8]);
                ldsm_x4(afr[mi], addr);
            }
            uint32_t bfr[8][2];
#pragma unroll
            for (int ni = 0; ni < 4; ni++) {
                uint32_t r[4];
                uint32_t addr = smem_u32(
                    &sB[buf][wn + ni * 16 + (lane & 7) + ((lane >> 4) & 1) * 8]
                       [k + ((lane >> 3) & 1) * 8]);
                ldsm_x4(r, addr);
                bfr[2 * ni][0]     = r[0];
                bfr[2 * ni][1]     = r[1];
                bfr[2 * ni + 1][0] = r[2];
                bfr[2 * ni + 1][1] = r[3];
            }
#pragma unroll
            for (int mi = 0; mi < 2; mi++)
#pragma unroll
                for (int nj = 0; nj < 8; nj++)
                    mma_bf16(acc[mi][nj], afr[mi], bfr[nj]);
        }
        __syncthreads();
    }

#pragma unroll
    for (int mi = 0; mi < 2; mi++) {
#pragma unroll
        for (int nj = 0; nj < 8; nj++) {
            int row0 = bm * 128 + wm + mi * 16 + (lane >> 2);
            int col  = bn * 128 + wn + nj * 8 + 2 * (lane & 3);
            float b0 = bias[col], b1 = bias[col + 1];
            float2 v0 = {acc[mi][nj][0] + b0, acc[mi][nj][1] + b1};
            float2 v1 = {acc[mi][nj][2] + b0, acc[mi][nj][3] + b1};
            if (relu) {
                v0.x = fmaxf(v0.x, 0.f); v0.y = fmaxf(v0.y, 0.f);
                v1.x = fmaxf(v1.x, 0.f); v1.y = fmaxf(v1.y, 0.f);
            }
            *(float2*)&C[(size_t)row0 * Ndim + col]       = v0;
            *(float2*)&C[(size_t)(row0 + 8) * Ndim + col] = v1;
        }
    }
}

// ---------------------------------------------------------------------------
// HMMA flash attention. grid = (B*NH, M/64), 128 threads (4 warps).
// ---------------------------------------------------------------------------
#define SWZ(row, ch) ((uint32_t)((row) * 128 + ((((ch) ^ ((row) & 7))) << 4)))

__global__ __launch_bounds__(128, 4)
void attn_hmma_kernel()
{
    __shared__ __nv_bfloat16 sQ[64 * 64];
    __shared__ __nv_bfloat16 sK[64 * 64];
    __shared__ __nv_bfloat16 sV[64 * 64];

    const int tid  = threadIdx.x;
    const int lane = tid & 31;
    const int wid  = tid >> 5;
    const int bh = blockIdx.x, qb = blockIdx.y;
    const int b = bh >> 4, h = bh & 15;
    const int g   = lane >> 2;   // 0..7
    const int tig = lane & 3;

    const uint32_t sQb = smem_u32(sQ);
    const uint32_t sKb = smem_u32(sK);
    const uint32_t sVb = smem_u32(sV);

    // ---- load Q tile: 64 rows x 64 cols fp32 -> bf16, swizzled ----
    {
        const float* Qg = g_Q + ((size_t)(b * M_ + qb * 64)) * DMODEL + h * DK;
#pragma unroll
        for (int it = 0; it < 4; it++) {
            int task = tid + 128 * it;          // 0..511
            int row = task >> 3, ch = task & 7;
            const float* src = Qg + (size_t)row * DMODEL + ch * 8;
            float4 v0 = *(const float4*)src;
            float4 v1 = *(const float4*)(src + 4);
            uint4 d;
            d.x = cvt_bf2(v0.x, v0.y);
            d.y = cvt_bf2(v0.z, v0.w);
            d.z = cvt_bf2(v1.x, v1.y);
            d.w = cvt_bf2(v1.z, v1.w);
            *(uint4*)((char*)sQ + SWZ(row, ch)) = d;
        }
    }
    __syncthreads();

    // ---- Q a-frags (persist across blocks) ----
    uint32_t qa[4][4];
#pragma unroll
    for (int kc = 0; kc < 4; kc++) {
        int row = wid * 16 + (lane & 15);
        int ch  = 2 * kc + (lane >> 4);
        ldsm_x4(qa[kc], sQb + SWZ(row, ch));
    }

    const int qrow0 = b * M_ + qb * 64 + wid * 16;
    const bool mq0 = g_mask[qrow0 + g] != 0;
    const bool mq8 = g_mask[qrow0 + g + 8] != 0;

    float o[8][4];
    float m0 = -1e30f, m8 = -1e30f, l0 = 0.0f, l8 = 0.0f;
#pragma unroll
    for (int nt = 0; nt < 8; nt++)
#pragma unroll
        for (int q = 0; q < 4; q++) o[nt][q] = 0.0f;

    const unsigned FULL = 0xffffffffu;

    for (int kb = 0; kb < M_ / 64; kb++) {
        __syncthreads();   // previous PV reads done

        // ---- load K,V tiles (fp32 -> bf16, swizzled) ----
        {
            const float* Kg = g_K + ((size_t)(b * M_ + kb * 64)) * DMODEL + h * DK;
            const float* Vg = g_V + ((size_t)(b * M_ + kb * 64)) * DMODEL + h * DK;
#pragma unroll
            for (int it = 0; it < 4; it++) {
                int task = tid + 128 * it;
                int row = task >> 3, ch = task & 7;
                size_t goff = (size_t)row * DMODEL + ch * 8;
                uint32_t soff = SWZ(row, ch);
                float4 k0v = *(const float4*)(Kg + goff);
                float4 k1v = *(const float4*)(Kg + goff + 4);
                uint4 dk;
                dk.x = cvt_bf2(k0v.x, k0v.y);
                dk.y = cvt_bf2(k0v.z, k0v.w);
                dk.z = cvt_bf2(k1v.x, k1v.y);
                dk.w = cvt_bf2(k1v.z, k1v.w);
                *(uint4*)((char*)sK + soff) = dk;
                float4 v0v = *(const float4*)(Vg + goff);
                float4 v1v = *(const float4*)(Vg + goff + 4);
                uint4 dv;
                dv.x = cvt_bf2(v0v.x, v0v.y);
                dv.y = cvt_bf2(v0v.z, v0v.w);
                dv.z = cvt_bf2(v1v.x, v1v.y);
                dv.w = cvt_bf2(v1v.z, v1v.w);
                *(uint4*)((char*)sV + soff) = dv;
            }
        }
        __syncthreads();

        // ---- S = Q K^T ----
        float s[8][4];
#pragma unroll
        for (int nt = 0; nt < 8; nt++)
#pragma unroll
            for (int q = 0; q < 4; q++) s[nt][q] = 0.0f;

#pragma unroll
        for (int kc = 0; kc < 4; kc++) {
#pragma unroll
            for (int ntp = 0; ntp < 4; ntp++) {
                uint32_t kbf[4];
                int rowk = ntp * 16 + ((lane >> 1) & 8) + (lane & 7);
                int chk  = 2 * kc + ((lane >> 3) & 1);
                ldsm_x4(kbf, sKb + SWZ(rowk, chk));
                mma_bf16(s[2 * ntp],     qa[kc], kbf);
                mma_bf16(s[2 * ntp + 1], qa[kc], kbf + 2);
            }
        }

        // ---- mask + scale ----
        const unsigned char* mkp = g_mask + b * M_ + kb * 64;
        float mn0 = m0, mn8 = m8;
#pragma unroll
        for (int nt = 0; nt < 8; nt++) {
            int c0 = nt * 8 + 2 * tig;
            bool k0 = mkp[c0] != 0, k1 = mkp[c0 + 1] != 0;
            s[nt][0] = (mq0 && k0) ? s[nt][0] * INV_D : MASKF;
            s[nt][1] = (mq0 && k1) ? s[nt][1] * INV_D : MASKF;
            s[nt][2] = (mq8 && k0) ? s[nt][2] * INV_D : MASKF;
            s[nt][3] = (mq8 && k1) ? s[nt][3] * INV_D : MASKF;
            mn0 = fmaxf(mn0, fmaxf(s[nt][0], s[nt][1]));
            mn8 = fmaxf(mn8, fmaxf(s[nt][2], s[nt][3]));
        }
        mn0 = fmaxf(mn0, __shfl_xor_sync(FULL, mn0, 1));
        mn0 = fmaxf(mn0, __shfl_xor_sync(FULL, mn0, 2));
        mn8 = fmaxf(mn8, __shfl_xor_sync(FULL, mn8, 1));
        mn8 = fmaxf(mn8, __shfl_xor_sync(FULL, mn8, 2));

        float corr0 = __expf(m0 - mn0);
        float corr8 = __expf(m8 - mn8);
        m0 = mn0; m8 = mn8;

        float sum0 = 0.0f, sum8 = 0.0f;
#pragma unroll
        for (int nt = 0; nt < 8; nt++) {
            s[nt][0] = __expf(s[nt][0] - mn0);
            s[nt][1] = __expf(s[nt][1] - mn0);
            s[nt][2] = __expf(s[nt][2] - mn8);
            s[nt][3] = __expf(s[nt][3] - mn8);
            sum0 += s[nt][0] + s[nt][1];
            sum8 += s[nt][2] + s[nt][3];
        }
        sum0 += __shfl_xor_sync(FULL, sum0, 1);
        sum0 += __shfl_xor_sync(FULL, sum0, 2);
        sum8 += __shfl_xor_sync(FULL, sum8, 1);
        sum8 += __shfl_xor_sync(FULL, sum8, 2);
        l0 = l0 * corr0 + sum0;
        l8 = l8 * corr8 + sum8;

        // ---- rescale O, pack P ----
#pragma unroll
        for (int nt = 0; nt < 8; nt++) {
            o[nt][0] *= corr0; o[nt][1] *= corr0;
            o[nt][2] *= corr8; o[nt][3] *= corr8;
        }
        uint32_t p[4][4];
#pragma unroll
        for (int kc = 0; kc < 4; kc++) {
            p[kc][0] = cvt_bf2(s[2 * kc][0],     s[2 * kc][1]);
            p[kc][1] = cvt_bf2(s[2 * kc][2],     s[2 * kc][3]);
            p[kc][2] = cvt_bf2(s[2 * kc + 1][0], s[2 * kc + 1][1]);
            p[kc][3] = cvt_bf2(s[2 * kc + 1][2], s[2 * kc + 1][3]);
        }

        // ---- O += P V ----
#pragma unroll
        for (int kc = 0; kc < 4; kc++) {
#pragma unroll
            for (int ntp = 0; ntp < 4; ntp++) {
                uint32_t vbf[4];
                int rowv = kc * 16 + (lane & 15);
                int chv  = 2 * ntp + (lane >> 4);
                ldsm_x4_t(vbf, sVb + SWZ(rowv, chv));
                mma_bf16(o[2 * ntp],     p[kc], vbf);
                mma_bf16(o[2 * ntp + 1], p[kc], vbf + 2);
            }
        }
    }

    // ---- finalize ----
    float inv0 = 1.0f / l0, inv8 = 1.0f / l8;
    float* Og = g_AO + ((size_t)(b * M_ + qb * 64 + wid * 16)) * DMODEL + h * DK;
#pragma unroll
    for (int nt = 0; nt < 8; nt++) {
        int c0 = nt * 8 + 2 * tig;
        float2 w0 = {o[nt][0] * inv0, o[nt][1] * inv0};
        float2 w1 = {o[nt][2] * inv8, o[nt][3] * inv8};
        *(float2*)&Og[(size_t)g * DMODEL + c0]       = w0;
        *(float2*)&Og[(size_t)(g + 8) * DMODEL + c0] = w1;
    }
}

// ---------------------------------------------------------------------------
// out = LayerNorm(a + b) * gamma + beta (unchanged)
// ---------------------------------------------------------------------------
__global__ __launch_bounds__(256)
void add_ln_kernel(const float* __restrict__ A, const float* __restrict__ Bv,
                   const float* __restrict__ gamma, const float* __restrict__ beta,
                   float* __restrict__ Out)
{
    const int row = blockIdx.x;
    const int t   = threadIdx.x;
    const float4* a4 = (const float4*)(A  + (size_t)row * DMODEL);
    const float4* b4 = (const float4*)(Bv + (size_t)row * DMODEL);

    float4 av = a4[t], bv = b4[t];
    float s0 = av.x + bv.x, s1 = av.y + bv.y, s2 = av.z + bv.z, s3 = av.w + bv.w;

    float sum = s0 + s1 + s2 + s3;
    float sq  = s0 * s0 + s1 * s1 + s2 * s2 + s3 * s3;
#pragma unroll
    for (int o = 16; o; o >>= 1) {
        sum += __shfl_xor_sync(0xffffffffu, sum, o);
        sq  += __shfl_xor_sync(0xffffffffu, sq,  o);
    }
    __shared__ float ssum[8], ssq[8];
    __shared__ float smu, srs;
    int wid = t >> 5, lane = t & 31;
    if (lane == 0) { ssum[wid] = sum; ssq[wid] = sq; }
    __syncthreads();
    if (t < 32) {
        float s2_ = (t < 8) ? ssum[t] : 0.0f;
        float q2_ = (t < 8) ? ssq[t]  : 0.0f;
#pragma unroll
        for (int o = 4; o; o >>= 1) {
            s2_ += __shfl_xor_sync(0xffffffffu, s2_, o);
            q2_ += __shfl_xor_sync(0xffffffffu, q2_, o);
        }
        if (t == 0) {
            float mu  = s2_ * (1.0f / DMODEL);
            float var = q2_ * (1.0f / DMODEL) - mu * mu;
            smu = mu;
            srs = rsqrtf(var + LN_EPS);
        }
    }
    __syncthreads();
    float mu = smu, rs = srs;
    float4 g = ((const float4*)gamma)[t];
    float4 be = ((const float4*)beta)[t];
    float4 o;
    o.x = (s0 - mu) * rs * g.x + be.x;
    o.y = (s1 - mu) * rs * g.y + be.y;
    o.z = (s2 - mu) * rs * g.z + be.z;
    o.w = (s3 - mu) * rs * g.w + be.w;
    ((float4*)(Out + (size_t)row * DMODEL))[t] = o;
}

// ---------------------------------------------------------------------------
// Launch
// ---------------------------------------------------------------------------
extern "C" void kernel_launch(void* const* d_in, const int* in_sizes, int n_in,
                              void* d_out, int out_size)
{
    (void)in_sizes; (void)n_in; (void)out_size;
    const float*         x    = (const float*)d_in[0];
    const unsigned char* mb   = (const unsigned char*)d_in[1];
    const float* Wq = (const float*)d_in[2];
    const float* bq = (const float*)d_in[3];
    const float* Wk = (const float*)d_in[4];
    const float* bk = (const float*)d_in[5];
    const float* Wv = (const float*)d_in[6];
    const float* bv = (const float*)d_in[7];
    const float* W1 = (const float*)d_in[8];
    const float* b1 = (const float*)d_in[9];
    const float* W2 = (const float*)d_in[10];
    const float* b2 = (const float*)d_in[11];
    const float* g1 = (const float*)d_in[12];
    const float* be1 = (const float*)d_in[13];
    const float* g2 = (const float*)d_in[14];
    const float* be2 = (const float*)d_in[15];
    float* out = (float*)d_out;

    float *pQ, *pK, *pV, *pAO, *pH1, *pF1, *pF2;
    __nv_bfloat16 *pAh, *pAl, *pBh, *pBl;
    cudaGetSymbolAddress((void**)&pQ,  g_Q);
    cudaGetSymbolAddress((void**)&pK,  g_K);
    cudaGetSymbolAddress((void**)&pV,  g_V);
    cudaGetSymbolAddress((void**)&pAO, g_AO);
    cudaGetSymbolAddress((void**)&pH1, g_H1);
    cudaGetSymbolAddress((void**)&pF1, g_F1);
    cudaGetSymbolAddress((void**)&pF2, g_F2);
    cudaGetSymbolAddress((void**)&pAh, g_Ah);
    cudaGetSymbolAddress((void**)&pAl, g_Al);
    cudaGetSymbolAddress((void**)&pBh, g_Bh);
    cudaGetSymbolAddress((void**)&pBl, g_Bl);

    mask_norm_kernel<<<1, 256>>>(mb, ROWS);

    // ---- split x (A operand for QKV) ----
    conv_split_kernel<<<(ROWS * DMODEL / 4 + 255) / 256, 256>>>(x, pAh, pAl, ROWS * DMODEL / 4);

    dim3 tg32(DMODEL / 32, DMODEL / 32);
    dim3 tb(32, 8);
    dim3 gqkv(DMODEL / 128, ROWS / 128);

    convT_split_kernel<<<tg32, tb>>>(Wq, pBh, pBl, DMODEL, DMODEL);
    hgemm_bf16x3_kernel<<<gqkv, 256>>>(pAh, pAl, pBh, pBl, bq, pQ, DMODEL, DMODEL, 0);
    convT_split_kernel<<<tg32, tb>>>(Wk, pBh, pBl, DMODEL, DMODEL);
    hgemm_bf16x3_kernel<<<gqkv, 256>>>(pAh, pAl, pBh, pBl, bk, pK, DMODEL, DMODEL, 0);
    convT_split_kernel<<<tg32, tb>>>(Wv, pBh, pBl, DMODEL, DMODEL);
    hgemm_bf16x3_kernel<<<gqkv, 256>>>(pAh, pAl, pBh, pBl, bv, pV, DMODEL, DMODEL, 0);

    // ---- attention (HMMA bf16) ----
    attn_hmma_kernel<<<dim3(B_ * NH, M_ / 64), 128>>>();

    // ---- h1 = LN(x + attn_out) ----
    add_ln_kernel<<<ROWS, 256>>>(x, pAO, g1, be1, pH1);

    // ---- FF1: relu(h1 @ W1 + b1) ----
    conv_split_kernel<<<(ROWS * DMODEL / 4 + 255) / 256, 256>>>(pH1, pAh, pAl, ROWS * DMODEL / 4);
    convT_split_kernel<<<dim3(FF / 32, DMODEL / 32), tb>>>(W1, pBh, pBl, DMODEL, FF);
    hgemm_bf16x3_kernel<<<dim3(FF / 128, ROWS / 128), 256>>>(
        pAh, pAl, pBh, pBl, b1, pF1, FF, DMODEL, 1);

    // ---- FF2: f1 @ W2 + b2 ----
    conv_split_kernel<<<(ROWS * FF / 4 + 255) / 256, 256>>>(pF1, pAh, pAl, ROWS * FF / 4);
    convT_split_kernel<<<dim3(DMODEL / 32, FF / 32), tb>>>(W2, pBh, pBl, FF, DMODEL);
    hgemm_bf16x3_kernel<<<dim3(DMODEL / 128, ROWS / 128), 256>>>(
        pAh, pAl, pBh, pBl, b2, pF2, DMODEL, FF, 0);

    // ---- out = LN(h1 + ff) ----
    add_ln_kernel<<<ROWS, 256>>>(pH1, pF2, g2, be2, out);
}